// round 10
// baseline (speedup 1.0000x reference)
#include <cuda_runtime.h>
#include <cuda_bf16.h>
#include <cstdint>

#define PK      16
#define NCENT   8192
#define IN_F    64
#define OUT_F   128
#define M_TILE  64
#define NTH     256
#define LDB     144          // A smem row pitch bytes (64 bf16 + 8 pad)

// B packed in mma-fragment order (PTX m16n8k16 .col B frag):
// index = k*8192 + wn8*1024 + nt2*512 + sel*256 + lane*8 + r   (u32 units)
__device__ __align__(128) uint32_t g_bfrag[PK * 8 * 2 * 2 * 32 * 8];   // 512KB

// ---------------- smem layout (bytes): A double-buffered, 45.5KB ------------
#define SM_KPTS   0
#define SM_COEF   256
#define SM_SRCS   (SM_COEF + 4096)
#define SM_A      8704
#define A_BYTES   (M_TILE * LDB)           // 9216
#define AH_OFF(s) (SM_A + (s) * 2 * A_BYTES)
#define AL_OFF(s) (AH_OFF(s) + A_BYTES)
#define SM_TOTAL  (SM_A + 4 * A_BYTES)     // 45568

__device__ __forceinline__ uint32_t smem_u32(const void* p) {
    uint32_t a;
    asm("{ .reg .u64 t; cvta.to.shared.u64 t, %1; cvt.u32.u64 %0, t; }"
        : "=r"(a) : "l"(p));
    return a;
}
__device__ __forceinline__ void ldsm4(uint32_t* r, uint32_t addr) {
    asm volatile("ldmatrix.sync.aligned.m8n8.x4.shared.b16 {%0,%1,%2,%3}, [%4];"
                 : "=r"(r[0]), "=r"(r[1]), "=r"(r[2]), "=r"(r[3]) : "r"(addr));
}
__device__ __forceinline__ void mma_bf16(float* c, const uint32_t* a, const uint32_t* b) {
    asm volatile("mma.sync.aligned.m16n8k16.row.col.f32.bf16.bf16.f32 "
                 "{%0,%1,%2,%3}, {%4,%5,%6,%7}, {%8,%9}, {%0,%1,%2,%3};"
                 : "+f"(c[0]), "+f"(c[1]), "+f"(c[2]), "+f"(c[3])
                 : "r"(a[0]), "r"(a[1]), "r"(a[2]), "r"(a[3]),
                   "r"(b[0]), "r"(b[1]));
}

// ---------------- pre-kernel: W -> fragment-packed hi/lo ---------------------
__global__ void wpack_kernel(const float* __restrict__ w) {
    int idx = blockIdx.x * blockDim.x + threadIdx.x;
    if (idx >= PK * 8 * 2 * 2 * 32 * 8) return;
    int r    = idx & 7;
    int lane = (idx >> 3) & 31;
    int sel  = (idx >> 8) & 1;
    int nt   = (idx >> 9) & 1;
    int wn   = (idx >> 10) & 7;
    int k    = idx >> 13;
    int ks   = r >> 1;
    int pair = r & 1;
    int o = wn * 16 + nt * 8 + (lane >> 2);
    int i = ks * 16 + (lane & 3) * 2 + pair * 8;
    float v0 = w[k * (IN_F * OUT_F) + i * OUT_F + o];
    float v1 = w[k * (IN_F * OUT_F) + (i + 1) * OUT_F + o];
    __nv_bfloat16 h0 = __float2bfloat16(v0);
    __nv_bfloat16 h1 = __float2bfloat16(v1);
    if (sel) {
        h0 = __float2bfloat16(v0 - __bfloat162float(h0));
        h1 = __float2bfloat16(v1 - __bfloat162float(h1));
    }
    __nv_bfloat162 p; p.x = h0; p.y = h1;
    g_bfrag[idx] = *(uint32_t*)&p;
}

// A staging: thread owns row arow = tid>>2, 16-float quarter aq = tid&3
#define A_CVT_STORE(stage)                                                  \
    do {                                                                    \
        float fv[16];                                                       \
        _Pragma("unroll")                                                   \
        for (int j = 0; j < 4; j++) {                                       \
            fv[j*4+0] = av[j].x * asc; fv[j*4+1] = av[j].y * asc;           \
            fv[j*4+2] = av[j].z * asc; fv[j*4+3] = av[j].w * asc;           \
        }                                                                   \
        uint32_t hi[8], lo[8];                                              \
        _Pragma("unroll")                                                   \
        for (int e2 = 0; e2 < 8; e2++) {                                    \
            float f0 = fv[e2 * 2], f1 = fv[e2 * 2 + 1];                     \
            __nv_bfloat16 h0 = __float2bfloat16(f0);                        \
            __nv_bfloat16 h1 = __float2bfloat16(f1);                        \
            __nv_bfloat162 hp; hp.x = h0; hp.y = h1;                        \
            __nv_bfloat162 lp;                                              \
            lp.x = __float2bfloat16(f0 - __bfloat162float(h0));             \
            lp.y = __float2bfloat16(f1 - __bfloat162float(h1));             \
            hi[e2] = *(uint32_t*)&hp;                                       \
            lo[e2] = *(uint32_t*)&lp;                                       \
        }                                                                   \
        *(uint4*)(sm + AH_OFF(stage) + arow * LDB + aq * 32) =              \
            make_uint4(hi[0], hi[1], hi[2], hi[3]);                         \
        *(uint4*)(sm + AH_OFF(stage) + arow * LDB + aq * 32 + 16) =         \
            make_uint4(hi[4], hi[5], hi[6], hi[7]);                         \
        *(uint4*)(sm + AL_OFF(stage) + arow * LDB + aq * 32) =              \
            make_uint4(lo[0], lo[1], lo[2], lo[3]);                         \
        *(uint4*)(sm + AL_OFF(stage) + arow * LDB + aq * 32 + 16) =         \
            make_uint4(lo[4], lo[5], lo[6], lo[7]);                         \
    } while (0)

// B prefetch offsets (u32 units) within a k/warp block: 8 hi then 8 lo uint4
__device__ __forceinline__ void b_prefetch(uint4 (&b)[16], const uint32_t* bb) {
    b[0]  = *(const uint4*)(bb + 0);    b[1]  = *(const uint4*)(bb + 4);
    b[2]  = *(const uint4*)(bb + 512);  b[3]  = *(const uint4*)(bb + 516);
    b[4]  = *(const uint4*)(bb + 1024); b[5]  = *(const uint4*)(bb + 1028);
    b[6]  = *(const uint4*)(bb + 1536); b[7]  = *(const uint4*)(bb + 1540);
    b[8]  = *(const uint4*)(bb + 256);  b[9]  = *(const uint4*)(bb + 260);
    b[10] = *(const uint4*)(bb + 768);  b[11] = *(const uint4*)(bb + 772);
    b[12] = *(const uint4*)(bb + 1280); b[13] = *(const uint4*)(bb + 1284);
    b[14] = *(const uint4*)(bb + 1792); b[15] = *(const uint4*)(bb + 1796);
}

struct StepCtx {
    char* sm; uint32_t smb;
    const float* x; const int* s_srcs; const float* s_coef;
    int arow, aq, wnp, lane;
    uint32_t a_row_off0, a_row_off1;
};

__device__ __forceinline__ void gemm_step(
    int k, uint4 (&bcur)[16], uint4 (&bnxt)[16],
    const StepCtx& c, float4 (&av)[4], float& asc,
    float (&acc)[2][4][4])
{
    char* sm = c.sm;
    const int arow = c.arow, aq = c.aq;
    const int cur = k & 1;

    // prefetch A[k+1] + B[k+1] (LDGs outstanding across compute)
    if (k + 1 < PK) {
        int src = c.s_srcs[arow * PK + k + 1];
        asc = c.s_coef[arow * PK + k + 1];
        const float4* xp = (const float4*)(c.x + (size_t)src * IN_F + aq * 16);
        #pragma unroll
        for (int j = 0; j < 4; j++) av[j] = xp[j];
        b_prefetch(bnxt, g_bfrag + (k + 1) * 8192 + c.wnp * 2048 + c.lane * 8);
    }

    // unpack current B fragments (register aliases)
    uint32_t bh[4][8], bl[4][8];
    #pragma unroll
    for (int j = 0; j < 4; j++) {
        bh[j][0] = bcur[2*j].x;   bh[j][1] = bcur[2*j].y;
        bh[j][2] = bcur[2*j].z;   bh[j][3] = bcur[2*j].w;
        bh[j][4] = bcur[2*j+1].x; bh[j][5] = bcur[2*j+1].y;
        bh[j][6] = bcur[2*j+1].z; bh[j][7] = bcur[2*j+1].w;
        bl[j][0] = bcur[8+2*j].x;   bl[j][1] = bcur[8+2*j].y;
        bl[j][2] = bcur[8+2*j].z;   bl[j][3] = bcur[8+2*j].w;
        bl[j][4] = bcur[8+2*j+1].x; bl[j][5] = bcur[8+2*j+1].y;
        bl[j][6] = bcur[8+2*j+1].z; bl[j][7] = bcur[8+2*j+1].w;
    }

    const uint32_t ah_b = c.smb + AH_OFF(cur);
    const uint32_t al_b = c.smb + AL_OFF(cur);
    const uint32_t aro[2] = {c.a_row_off0, c.a_row_off1};
    #pragma unroll
    for (int ks = 0; ks < 4; ks++) {
        const uint32_t i0 = ks * 32;
        uint32_t ah[2][4], al[2][4];
        #pragma unroll
        for (int mt = 0; mt < 2; mt++) {
            ldsm4(ah[mt], ah_b + aro[mt] + i0);
            ldsm4(al[mt], al_b + aro[mt] + i0);
        }
        #pragma unroll
        for (int mt = 0; mt < 2; mt++)
            #pragma unroll
            for (int nt = 0; nt < 4; nt++) {
                mma_bf16(acc[mt][nt], ah[mt], &bh[nt][ks * 2]);
                mma_bf16(acc[mt][nt], ah[mt], &bl[nt][ks * 2]);
                mma_bf16(acc[mt][nt], al[mt], &bh[nt][ks * 2]);
            }
    }

    if (k + 1 < PK) A_CVT_STORE(cur ^ 1);
    __syncthreads();
}

// ---------------- main fused kernel ------------------------------------------
__global__ __launch_bounds__(NTH, 1) void kpconv_hmma_kernel(
    const float* __restrict__ x,
    const float* __restrict__ pos,
    const int*   __restrict__ edge_src,
    const int*   __restrict__ edge_tgt,
    const float* __restrict__ kernel_pts,
    float* __restrict__ out)
{
    extern __shared__ char sm[];
    const uint32_t smb = smem_u32(sm);
    float* s_kpts = (float*)(sm + SM_KPTS);
    float* s_coef = (float*)(sm + SM_COEF);
    int*   s_srcs = (int*)(sm + SM_SRCS);

    const int tid  = threadIdx.x;
    const int wid  = tid >> 5;
    const int lane = tid & 31;
    const int c0   = blockIdx.x * M_TILE;

    if (tid < PK * 3) s_kpts[tid] = kernel_pts[tid];
    for (int i = tid; i < M_TILE * PK; i += NTH) s_coef[i] = 0.0f;
    __syncthreads();

    // ---- geometry ----
    #pragma unroll
    for (int j = 0; j < (M_TILE * PK) / NTH; j++) {
        int el = tid + j * NTH;
        int e  = c0 * PK + el;
        int s  = edge_src[e];
        int t  = edge_tgt[e];
        s_srcs[el] = s;
        float rx = pos[3 * t + 0] - pos[3 * s + 0];
        float ry = pos[3 * t + 1] - pos[3 * s + 1];
        float rz = pos[3 * t + 2] - pos[3 * s + 2];
        float best = 3.4e38f; int bk = 0;
        #pragma unroll
        for (int kp = 0; kp < PK; kp++) {
            float dx = rx - s_kpts[3 * kp + 0];
            float dy = ry - s_kpts[3 * kp + 1];
            float dz = rz - s_kpts[3 * kp + 2];
            float d2 = dx * dx + dy * dy + dz * dz;
            if (d2 < best) { best = d2; bk = kp; }
        }
        float w = fmaxf(1.0f - sqrtf(best) * 1.5f, 0.0f);
        atomicAdd(&s_coef[(el & ~(PK - 1)) + bk], w);
    }
    __syncthreads();

    // 8 warps: wm = wid&1 (2 x 32 rows), wnp = wid>>1 (4 x 32 cols)
    const int wm  = wid & 1;
    const int wnp = wid >> 1;

    StepCtx ctx;
    ctx.sm = sm; ctx.smb = smb;
    ctx.x = x; ctx.s_srcs = s_srcs; ctx.s_coef = s_coef;
    ctx.arow = tid >> 2; ctx.aq = tid & 3; ctx.wnp = wnp; ctx.lane = lane;
    ctx.a_row_off0 = (uint32_t)((wm * 32 + 0  + (lane & 15)) * LDB + (lane >> 4) * 16);
    ctx.a_row_off1 = (uint32_t)((wm * 32 + 16 + (lane & 15)) * LDB + (lane >> 4) * 16);

    float acc[2][4][4];
    #pragma unroll
    for (int mt = 0; mt < 2; mt++)
        #pragma unroll
        for (int nt = 0; nt < 4; nt++)
            #pragma unroll
            for (int q = 0; q < 4; q++) acc[mt][nt][q] = 0.0f;

    const int arow = ctx.arow, aq = ctx.aq;
    float4 av[4];
    float  asc;
    uint4  b0[16], b1[16];

    // prologue: A[0] staged, B[0] -> b0
    {
        int src = s_srcs[arow * PK + 0];
        asc = s_coef[arow * PK + 0];
        const float4* xp = (const float4*)(x + (size_t)src * IN_F + aq * 16);
        #pragma unroll
        for (int j = 0; j < 4; j++) av[j] = xp[j];
        b_prefetch(b0, g_bfrag + wnp * 2048 + lane * 8);
        A_CVT_STORE(0);
    }
    __syncthreads();

    #pragma unroll 1
    for (int kk = 0; kk < PK; kk += 2) {
        gemm_step(kk,     b0, b1, ctx, av, asc, acc);
        gemm_step(kk + 1, b1, b0, ctx, av, asc, acc);
    }

    // ---- epilogue ----
    #pragma unroll
    for (int mt = 0; mt < 2; mt++) {
        int row = c0 + wm * 32 + mt * 16 + (lane >> 2);
        #pragma unroll
        for (int nt = 0; nt < 4; nt++) {
            int col = wnp * 32 + nt * 8 + (lane & 3) * 2;
            float2 v0 = make_float2(acc[mt][nt][0], acc[mt][nt][1]);
            float2 v1 = make_float2(acc[mt][nt][2], acc[mt][nt][3]);
            *(float2*)(out + (size_t)row * OUT_F + col)       = v0;
            *(float2*)(out + (size_t)(row + 8) * OUT_F + col) = v1;
        }
    }
}

extern "C" void kernel_launch(void* const* d_in, const int* in_sizes, int n_in,
                              void* d_out, int out_size) {
    const float* x             = (const float*)d_in[0];
    const float* pos           = (const float*)d_in[1];
    const int*   edge_src      = (const int*)d_in[2];
    const int*   edge_tgt      = (const int*)d_in[3];
    const float* kernel_pts    = (const float*)d_in[4];
    const float* kernel_weight = (const float*)d_in[5];
    float* out = (float*)d_out;

    wpack_kernel<<<(PK * 8 * 2 * 2 * 32 * 8 + 255) / 256, 256>>>(kernel_weight);

    cudaFuncSetAttribute(kpconv_hmma_kernel,
                         cudaFuncAttributeMaxDynamicSharedMemorySize, SM_TOTAL);
    kpconv_hmma_kernel<<<NCENT / M_TILE, NTH, SM_TOTAL>>>(
        x, pos, edge_src, edge_tgt, kernel_pts, out);
}

// round 11
// speedup vs baseline: 1.0072x; 1.0072x over previous
#include <cuda_runtime.h>
#include <cuda_bf16.h>
#include <cstdint>

#define PK      16
#define NCENT   8192
#define IN_F    64
#define OUT_F   128
#define M_TILE  64
#define NTH     512
#define LDB     144          // A smem row pitch bytes (64 bf16 + 8 pad)

// B packed in mma-fragment order (PTX m16n8k16 .col B frag):
// index = k*8192 + wn8*1024 + nt2*512 + sel*256 + lane*8 + r   (u32 units)
__device__ __align__(128) uint32_t g_bfrag[PK * 8 * 2 * 2 * 32 * 8];   // 512KB

// ---------------- smem layout (bytes): IDENTICAL to passing R9/R10 ----------
#define SM_KPTS   0
#define SM_COEF   256
#define SM_SRCS   (SM_COEF + 4096)
#define SM_A      8704
#define A_BYTES   (M_TILE * LDB)           // 9216
#define AH_OFF(s) (SM_A + (s) * 2 * A_BYTES)
#define AL_OFF(s) (AH_OFF(s) + A_BYTES)
#define SM_TOTAL  (SM_A + 4 * A_BYTES)     // 45568

// named barriers: full[s] = 1+s, empty[s] = 3+s, all-thread count
#define BAR_SYNC(id)   asm volatile("bar.sync %0, 512;"   :: "r"(id) : "memory")
#define BAR_ARRIVE(id) asm volatile("bar.arrive %0, 512;" :: "r"(id) : "memory")

__device__ __forceinline__ uint32_t smem_u32(const void* p) {
    uint32_t a;
    asm("{ .reg .u64 t; cvta.to.shared.u64 t, %1; cvt.u32.u64 %0, t; }"
        : "=r"(a) : "l"(p));
    return a;
}
__device__ __forceinline__ void ldsm4(uint32_t* r, uint32_t addr) {
    asm volatile("ldmatrix.sync.aligned.m8n8.x4.shared.b16 {%0,%1,%2,%3}, [%4];"
                 : "=r"(r[0]), "=r"(r[1]), "=r"(r[2]), "=r"(r[3]) : "r"(addr));
}
__device__ __forceinline__ void mma_bf16(float* c, const uint32_t* a, const uint32_t* b) {
    asm volatile("mma.sync.aligned.m16n8k16.row.col.f32.bf16.bf16.f32 "
                 "{%0,%1,%2,%3}, {%4,%5,%6,%7}, {%8,%9}, {%0,%1,%2,%3};"
                 : "+f"(c[0]), "+f"(c[1]), "+f"(c[2]), "+f"(c[3])
                 : "r"(a[0]), "r"(a[1]), "r"(a[2]), "r"(a[3]),
                   "r"(b[0]), "r"(b[1]));
}

// ---------------- pre-kernel: W -> fragment-packed hi/lo ---------------------
__global__ void wpack_kernel(const float* __restrict__ w) {
    int idx = blockIdx.x * blockDim.x + threadIdx.x;
    if (idx >= PK * 8 * 2 * 2 * 32 * 8) return;
    int r    = idx & 7;
    int lane = (idx >> 3) & 31;
    int sel  = (idx >> 8) & 1;
    int nt   = (idx >> 9) & 1;
    int wn   = (idx >> 10) & 7;
    int k    = idx >> 13;
    int ks   = r >> 1;
    int pair = r & 1;
    int o = wn * 16 + nt * 8 + (lane >> 2);
    int i = ks * 16 + (lane & 3) * 2 + pair * 8;
    float v0 = w[k * (IN_F * OUT_F) + i * OUT_F + o];
    float v1 = w[k * (IN_F * OUT_F) + (i + 1) * OUT_F + o];
    __nv_bfloat16 h0 = __float2bfloat16(v0);
    __nv_bfloat16 h1 = __float2bfloat16(v1);
    if (sel) {
        h0 = __float2bfloat16(v0 - __bfloat162float(h0));
        h1 = __float2bfloat16(v1 - __bfloat162float(h1));
    }
    __nv_bfloat162 p; p.x = h0; p.y = h1;
    g_bfrag[idx] = *(uint32_t*)&p;
}

// B prefetch: 8 hi then 8 lo uint4
__device__ __forceinline__ void b_prefetch(uint4 (&b)[16], const uint32_t* bb) {
    b[0]  = *(const uint4*)(bb + 0);    b[1]  = *(const uint4*)(bb + 4);
    b[2]  = *(const uint4*)(bb + 512);  b[3]  = *(const uint4*)(bb + 516);
    b[4]  = *(const uint4*)(bb + 1024); b[5]  = *(const uint4*)(bb + 1028);
    b[6]  = *(const uint4*)(bb + 1536); b[7]  = *(const uint4*)(bb + 1540);
    b[8]  = *(const uint4*)(bb + 256);  b[9]  = *(const uint4*)(bb + 260);
    b[10] = *(const uint4*)(bb + 768);  b[11] = *(const uint4*)(bb + 772);
    b[12] = *(const uint4*)(bb + 1280); b[13] = *(const uint4*)(bb + 1284);
    b[14] = *(const uint4*)(bb + 1792); b[15] = *(const uint4*)(bb + 1796);
}

// ---------------- main fused kernel ------------------------------------------
__global__ __launch_bounds__(NTH, 1) void kpconv_hmma_kernel(
    const float* __restrict__ x,
    const float* __restrict__ pos,
    const int*   __restrict__ edge_src,
    const int*   __restrict__ edge_tgt,
    const float* __restrict__ kernel_pts,
    float* __restrict__ out)
{
    extern __shared__ char sm[];
    const uint32_t smb = smem_u32(sm);
    float* s_kpts = (float*)(sm + SM_KPTS);
    float* s_coef = (float*)(sm + SM_COEF);
    int*   s_srcs = (int*)(sm + SM_SRCS);

    const int tid  = threadIdx.x;
    const int wid  = tid >> 5;
    const int lane = tid & 31;
    const int c0   = blockIdx.x * M_TILE;

    if (tid < PK * 3) s_kpts[tid] = kernel_pts[tid];
    for (int i = tid; i < M_TILE * PK; i += NTH) s_coef[i] = 0.0f;
    __syncthreads();

    // ---- geometry (all 512 threads) ----
    #pragma unroll
    for (int j = 0; j < (M_TILE * PK) / NTH; j++) {
        int el = tid + j * NTH;
        int e  = c0 * PK + el;
        int s  = edge_src[e];
        int t  = edge_tgt[e];
        s_srcs[el] = s;
        float rx = pos[3 * t + 0] - pos[3 * s + 0];
        float ry = pos[3 * t + 1] - pos[3 * s + 1];
        float rz = pos[3 * t + 2] - pos[3 * s + 2];
        float best = 3.4e38f; int bk = 0;
        #pragma unroll
        for (int kp = 0; kp < PK; kp++) {
            float dx = rx - s_kpts[3 * kp + 0];
            float dy = ry - s_kpts[3 * kp + 1];
            float dz = rz - s_kpts[3 * kp + 2];
            float d2 = dx * dx + dy * dy + dz * dz;
            if (d2 < best) { best = d2; bk = kp; }
        }
        float w = fmaxf(1.0f - sqrtf(best) * 1.5f, 0.0f);
        atomicAdd(&s_coef[(el & ~(PK - 1)) + bk], w);
    }
    __syncthreads();     // last full-CTA barrier; roles split below

    if (wid >= 8) {
        // ================= PRODUCER (warps 8..15, 256 threads) ===============
        const int ptid = tid - 256;
        const int arow = ptid >> 2;       // row 0..63
        const int aq   = ptid & 3;        // 16-float quarter
        float4 av[4];
        float  asc;

        // prologue: LDG x-row for k=0
        {
            int src = s_srcs[arow * PK + 0];
            asc = s_coef[arow * PK + 0];
            const float4* xp = (const float4*)(x + (size_t)src * IN_F + aq * 16);
            #pragma unroll
            for (int j = 0; j < 4; j++) av[j] = xp[j];
        }

        #pragma unroll 1
        for (int k = 0; k < PK; k++) {
            const int s = k & 1;
            if (k >= 2) BAR_SYNC(3 + s);          // wait stage free

            // cvt + store A[k] (data already in av/asc)
            {
                float fv[16];
                #pragma unroll
                for (int j = 0; j < 4; j++) {
                    fv[j*4+0] = av[j].x * asc; fv[j*4+1] = av[j].y * asc;
                    fv[j*4+2] = av[j].z * asc; fv[j*4+3] = av[j].w * asc;
                }
                uint32_t hi[8], lo[8];
                #pragma unroll
                for (int e2 = 0; e2 < 8; e2++) {
                    float f0 = fv[e2 * 2], f1 = fv[e2 * 2 + 1];
                    __nv_bfloat16 h0 = __float2bfloat16(f0);
                    __nv_bfloat16 h1 = __float2bfloat16(f1);
                    __nv_bfloat162 hp; hp.x = h0; hp.y = h1;
                    __nv_bfloat162 lp;
                    lp.x = __float2bfloat16(f0 - __bfloat162float(h0));
                    lp.y = __float2bfloat16(f1 - __bfloat162float(h1));
                    hi[e2] = *(uint32_t*)&hp;
                    lo[e2] = *(uint32_t*)&lp;
                }
                *(uint4*)(sm + AH_OFF(s) + arow * LDB + aq * 32) =
                    make_uint4(hi[0], hi[1], hi[2], hi[3]);
                *(uint4*)(sm + AH_OFF(s) + arow * LDB + aq * 32 + 16) =
                    make_uint4(hi[4], hi[5], hi[6], hi[7]);
                *(uint4*)(sm + AL_OFF(s) + arow * LDB + aq * 32) =
                    make_uint4(lo[0], lo[1], lo[2], lo[3]);
                *(uint4*)(sm + AL_OFF(s) + arow * LDB + aq * 32 + 16) =
                    make_uint4(lo[4], lo[5], lo[6], lo[7]);
            }
            BAR_ARRIVE(1 + s);                    // stage full

            // LDG x-row for k+1 (in flight during next empty wait)
            if (k + 1 < PK) {
                int src = s_srcs[arow * PK + k + 1];
                asc = s_coef[arow * PK + k + 1];
                const float4* xp = (const float4*)(x + (size_t)src * IN_F + aq * 16);
                #pragma unroll
                for (int j = 0; j < 4; j++) av[j] = xp[j];
            }
        }
        return;   // producers exit; all their barrier arrivals already posted
    }

    // ================= CONSUMER (warps 0..7) =================================
    const int wm  = wid & 1;          // 2 x 32 rows
    const int wnp = wid >> 1;         // 4 x 32 cols
    const uint32_t a_row_off[2] = {
        (uint32_t)((wm * 32 + 0  + (lane & 15)) * LDB + (lane >> 4) * 16),
        (uint32_t)((wm * 32 + 16 + (lane & 15)) * LDB + (lane >> 4) * 16)};

    float acc[2][4][4];
    #pragma unroll
    for (int mt = 0; mt < 2; mt++)
        #pragma unroll
        for (int nt = 0; nt < 4; nt++)
            #pragma unroll
            for (int q = 0; q < 4; q++) acc[mt][nt][q] = 0.0f;

    uint4 bfr[16];
    b_prefetch(bfr, g_bfrag + wnp * 2048 + lane * 8);   // B[0]

    #pragma unroll 1
    for (int k = 0; k < PK; k++) {
        const int s = k & 1;
        BAR_SYNC(1 + s);                          // wait A[k] staged

        // unpack current B fragments
        uint32_t bh[4][8], bl[4][8];
        #pragma unroll
        for (int j = 0; j < 4; j++) {
            bh[j][0] = bfr[2*j].x;   bh[j][1] = bfr[2*j].y;
            bh[j][2] = bfr[2*j].z;   bh[j][3] = bfr[2*j].w;
            bh[j][4] = bfr[2*j+1].x; bh[j][5] = bfr[2*j+1].y;
            bh[j][6] = bfr[2*j+1].z; bh[j][7] = bfr[2*j+1].w;
            bl[j][0] = bfr[8+2*j].x;   bl[j][1] = bfr[8+2*j].y;
            bl[j][2] = bfr[8+2*j].z;   bl[j][3] = bfr[8+2*j].w;
            bl[j][4] = bfr[8+2*j+1].x; bl[j][5] = bfr[8+2*j+1].y;
            bl[j][6] = bfr[8+2*j+1].z; bl[j][7] = bfr[8+2*j+1].w;
        }

        const uint32_t ah_b = smb + AH_OFF(s);
        const uint32_t al_b = smb + AL_OFF(s);
        #pragma unroll
        for (int ks = 0; ks < 4; ks++) {
            const uint32_t i0 = ks * 32;
            uint32_t ah[2][4], al[2][4];
            #pragma unroll
            for (int mt = 0; mt < 2; mt++) {
                ldsm4(ah[mt], ah_b + a_row_off[mt] + i0);
                ldsm4(al[mt], al_b + a_row_off[mt] + i0);
            }
            #pragma unroll
            for (int mt = 0; mt < 2; mt++)
                #pragma unroll
                for (int nt = 0; nt < 4; nt++) {
                    mma_bf16(acc[mt][nt], ah[mt], &bh[nt][ks * 2]);
                    mma_bf16(acc[mt][nt], ah[mt], &bl[nt][ks * 2]);
                    mma_bf16(acc[mt][nt], al[mt], &bh[nt][ks * 2]);
                }
        }
        BAR_ARRIVE(3 + s);                        // stage free

        // B[k+1] LDGs in flight during next full-wait
        if (k + 1 < PK)
            b_prefetch(bfr, g_bfrag + (k + 1) * 8192 + wnp * 2048 + lane * 8);
    }

    // ---- epilogue (consumers only) ----
    #pragma unroll
    for (int mt = 0; mt < 2; mt++) {
        int row = c0 + wm * 32 + mt * 16 + (lane >> 2);
        #pragma unroll
        for (int nt = 0; nt < 4; nt++) {
            int col = wnp * 32 + nt * 8 + (lane & 3) * 2;
            float2 v0 = make_float2(acc[mt][nt][0], acc[mt][nt][1]);
            float2 v1 = make_float2(acc[mt][nt][2], acc[mt][nt][3]);
            *(float2*)(out + (size_t)row * OUT_F + col)       = v0;
            *(float2*)(out + (size_t)(row + 8) * OUT_F + col) = v1;
        }
    }
}

extern "C" void kernel_launch(void* const* d_in, const int* in_sizes, int n_in,
                              void* d_out, int out_size) {
    const float* x             = (const float*)d_in[0];
    const float* pos           = (const float*)d_in[1];
    const int*   edge_src      = (const int*)d_in[2];
    const int*   edge_tgt      = (const int*)d_in[3];
    const float* kernel_pts    = (const float*)d_in[4];
    const float* kernel_weight = (const float*)d_in[5];
    float* out = (float*)d_out;

    wpack_kernel<<<(PK * 8 * 2 * 2 * 32 * 8 + 255) / 256, 256>>>(kernel_weight);

    cudaFuncSetAttribute(kpconv_hmma_kernel,
                         cudaFuncAttributeMaxDynamicSharedMemorySize, SM_TOTAL);
    kpconv_hmma_kernel<<<NCENT / M_TILE, NTH, SM_TOTAL>>>(
        x, pos, edge_src, edge_tgt, kernel_pts, out);
}

// round 12
// speedup vs baseline: 1.0197x; 1.0124x over previous
#include <cuda_runtime.h>
#include <cuda_bf16.h>
#include <cstdint>

#define PK      16
#define NCENT   8192
#define IN_F    64
#define OUT_F   128
#define M_TILE  32
#define NTH     128
#define LDB     144          // A smem row pitch bytes (64 bf16 + 8 pad)

// B packed in mma-fragment order (PTX m16n8k16 .col B frag):
// index = k*8192 + wn8*1024 + nt2*512 + sel*256 + lane*8 + r   (u32 units)
__device__ __align__(128) uint32_t g_bfrag[PK * 8 * 2 * 2 * 32 * 8];   // 512KB

// ---------------- smem layout (bytes): A double-buffered, 22.8KB/CTA --------
#define SM_KPTS   0
#define SM_COEF   256                      // 32*16 f32 = 2048
#define SM_SRCS   (SM_COEF + 2048)         // 32*16 int = 2048
#define SM_A      4352
#define A_BYTES   (M_TILE * LDB)           // 4608
#define AH_OFF(s) (SM_A + (s) * 2 * A_BYTES)
#define AL_OFF(s) (AH_OFF(s) + A_BYTES)
#define SM_TOTAL  (SM_A + 4 * A_BYTES)     // 22784

__device__ __forceinline__ uint32_t smem_u32(const void* p) {
    uint32_t a;
    asm("{ .reg .u64 t; cvta.to.shared.u64 t, %1; cvt.u32.u64 %0, t; }"
        : "=r"(a) : "l"(p));
    return a;
}
__device__ __forceinline__ void ldsm4(uint32_t* r, uint32_t addr) {
    asm volatile("ldmatrix.sync.aligned.m8n8.x4.shared.b16 {%0,%1,%2,%3}, [%4];"
                 : "=r"(r[0]), "=r"(r[1]), "=r"(r[2]), "=r"(r[3]) : "r"(addr));
}
__device__ __forceinline__ void mma_bf16(float* c, const uint32_t* a, const uint32_t* b) {
    asm volatile("mma.sync.aligned.m16n8k16.row.col.f32.bf16.bf16.f32 "
                 "{%0,%1,%2,%3}, {%4,%5,%6,%7}, {%8,%9}, {%0,%1,%2,%3};"
                 : "+f"(c[0]), "+f"(c[1]), "+f"(c[2]), "+f"(c[3])
                 : "r"(a[0]), "r"(a[1]), "r"(a[2]), "r"(a[3]),
                   "r"(b[0]), "r"(b[1]));
}

// ---------------- pre-kernel: W -> fragment-packed hi/lo ---------------------
__global__ void wpack_kernel(const float* __restrict__ w) {
    int idx = blockIdx.x * blockDim.x + threadIdx.x;
    if (idx >= PK * 8 * 2 * 2 * 32 * 8) return;
    int r    = idx & 7;
    int lane = (idx >> 3) & 31;
    int sel  = (idx >> 8) & 1;
    int nt   = (idx >> 9) & 1;
    int wn   = (idx >> 10) & 7;
    int k    = idx >> 13;
    int ks   = r >> 1;
    int pair = r & 1;
    int o = wn * 16 + nt * 8 + (lane >> 2);
    int i = ks * 16 + (lane & 3) * 2 + pair * 8;
    float v0 = w[k * (IN_F * OUT_F) + i * OUT_F + o];
    float v1 = w[k * (IN_F * OUT_F) + (i + 1) * OUT_F + o];
    __nv_bfloat16 h0 = __float2bfloat16(v0);
    __nv_bfloat16 h1 = __float2bfloat16(v1);
    if (sel) {
        h0 = __float2bfloat16(v0 - __bfloat162float(h0));
        h1 = __float2bfloat16(v1 - __bfloat162float(h1));
    }
    __nv_bfloat162 p; p.x = h0; p.y = h1;
    g_bfrag[idx] = *(uint32_t*)&p;
}

// A staging: thread owns row arow = tid>>2 (0..31), 16-float quarter aq = tid&3
#define A_CVT_STORE(stage)                                                  \
    do {                                                                    \
        float fv[16];                                                       \
        _Pragma("unroll")                                                   \
        for (int j = 0; j < 4; j++) {                                       \
            fv[j*4+0] = av[j].x * asc; fv[j*4+1] = av[j].y * asc;           \
            fv[j*4+2] = av[j].z * asc; fv[j*4+3] = av[j].w * asc;           \
        }                                                                   \
        uint32_t hi[8], lo[8];                                              \
        _Pragma("unroll")                                                   \
        for (int e2 = 0; e2 < 8; e2++) {                                    \
            float f0 = fv[e2 * 2], f1 = fv[e2 * 2 + 1];                     \
            __nv_bfloat16 h0 = __float2bfloat16(f0);                        \
            __nv_bfloat16 h1 = __float2bfloat16(f1);                        \
            __nv_bfloat162 hp; hp.x = h0; hp.y = h1;                        \
            __nv_bfloat162 lp;                                              \
            lp.x = __float2bfloat16(f0 - __bfloat162float(h0));             \
            lp.y = __float2bfloat16(f1 - __bfloat162float(h1));             \
            hi[e2] = *(uint32_t*)&hp;                                       \
            lo[e2] = *(uint32_t*)&lp;                                       \
        }                                                                   \
        *(uint4*)(sm + AH_OFF(stage) + arow * LDB + aq * 32) =              \
            make_uint4(hi[0], hi[1], hi[2], hi[3]);                         \
        *(uint4*)(sm + AH_OFF(stage) + arow * LDB + aq * 32 + 16) =         \
            make_uint4(hi[4], hi[5], hi[6], hi[7]);                         \
        *(uint4*)(sm + AL_OFF(stage) + arow * LDB + aq * 32) =              \
            make_uint4(lo[0], lo[1], lo[2], lo[3]);                         \
        *(uint4*)(sm + AL_OFF(stage) + arow * LDB + aq * 32 + 16) =         \
            make_uint4(lo[4], lo[5], lo[6], lo[7]);                         \
    } while (0)

// B prefetch offsets (u32 units): 8 hi then 8 lo uint4 (spans 2 wn groups)
__device__ __forceinline__ void b_prefetch(uint4 (&b)[16], const uint32_t* bb) {
    b[0]  = *(const uint4*)(bb + 0);    b[1]  = *(const uint4*)(bb + 4);
    b[2]  = *(const uint4*)(bb + 512);  b[3]  = *(const uint4*)(bb + 516);
    b[4]  = *(const uint4*)(bb + 1024); b[5]  = *(const uint4*)(bb + 1028);
    b[6]  = *(const uint4*)(bb + 1536); b[7]  = *(const uint4*)(bb + 1540);
    b[8]  = *(const uint4*)(bb + 256);  b[9]  = *(const uint4*)(bb + 260);
    b[10] = *(const uint4*)(bb + 768);  b[11] = *(const uint4*)(bb + 772);
    b[12] = *(const uint4*)(bb + 1280); b[13] = *(const uint4*)(bb + 1284);
    b[14] = *(const uint4*)(bb + 1792); b[15] = *(const uint4*)(bb + 1796);
}

struct StepCtx {
    char* sm; uint32_t smb;
    const float* x; const int* s_srcs; const float* s_coef;
    int arow, aq, wnp, lane;
    uint32_t a_row_off0, a_row_off1;
};

__device__ __forceinline__ void gemm_step(
    int k, uint4 (&bcur)[16], uint4 (&bnxt)[16],
    const StepCtx& c, float4 (&av)[4], float& asc,
    float (&acc)[2][4][4])
{
    char* sm = c.sm;
    const int arow = c.arow, aq = c.aq;
    const int cur = k & 1;

    // prefetch A[k+1] + B[k+1] (LDGs outstanding across compute)
    if (k + 1 < PK) {
        int src = c.s_srcs[arow * PK + k + 1];
        asc = c.s_coef[arow * PK + k + 1];
        const float4* xp = (const float4*)(c.x + (size_t)src * IN_F + aq * 16);
        #pragma unroll
        for (int j = 0; j < 4; j++) av[j] = xp[j];
        b_prefetch(bnxt, g_bfrag + (k + 1) * 8192 + c.wnp * 2048 + c.lane * 8);
    }

    // unpack current B fragments (register aliases)
    uint32_t bh[4][8], bl[4][8];
    #pragma unroll
    for (int j = 0; j < 4; j++) {
        bh[j][0] = bcur[2*j].x;   bh[j][1] = bcur[2*j].y;
        bh[j][2] = bcur[2*j].z;   bh[j][3] = bcur[2*j].w;
        bh[j][4] = bcur[2*j+1].x; bh[j][5] = bcur[2*j+1].y;
        bh[j][6] = bcur[2*j+1].z; bh[j][7] = bcur[2*j+1].w;
        bl[j][0] = bcur[8+2*j].x;   bl[j][1] = bcur[8+2*j].y;
        bl[j][2] = bcur[8+2*j].z;   bl[j][3] = bcur[8+2*j].w;
        bl[j][4] = bcur[8+2*j+1].x; bl[j][5] = bcur[8+2*j+1].y;
        bl[j][6] = bcur[8+2*j+1].z; bl[j][7] = bcur[8+2*j+1].w;
    }

    const uint32_t ah_b = c.smb + AH_OFF(cur);
    const uint32_t al_b = c.smb + AL_OFF(cur);
    const uint32_t aro[2] = {c.a_row_off0, c.a_row_off1};
    #pragma unroll
    for (int ks = 0; ks < 4; ks++) {
        const uint32_t i0 = ks * 32;
        uint32_t ah[2][4], al[2][4];
        #pragma unroll
        for (int mt = 0; mt < 2; mt++) {
            ldsm4(ah[mt], ah_b + aro[mt] + i0);
            ldsm4(al[mt], al_b + aro[mt] + i0);
        }
        #pragma unroll
        for (int mt = 0; mt < 2; mt++)
            #pragma unroll
            for (int nt = 0; nt < 4; nt++) {
                mma_bf16(acc[mt][nt], ah[mt], &bh[nt][ks * 2]);
                mma_bf16(acc[mt][nt], ah[mt], &bl[nt][ks * 2]);
                mma_bf16(acc[mt][nt], al[mt], &bh[nt][ks * 2]);
            }
    }

    if (k + 1 < PK) A_CVT_STORE(cur ^ 1);
    __syncthreads();
}

// ---------------- main fused kernel ------------------------------------------
__global__ __launch_bounds__(NTH, 2) void kpconv_hmma_kernel(
    const float* __restrict__ x,
    const float* __restrict__ pos,
    const int*   __restrict__ edge_src,
    const int*   __restrict__ edge_tgt,
    const float* __restrict__ kernel_pts,
    float* __restrict__ out)
{
    extern __shared__ char sm[];
    const uint32_t smb = smem_u32(sm);
    float* s_kpts = (float*)(sm + SM_KPTS);
    float* s_coef = (float*)(sm + SM_COEF);
    int*   s_srcs = (int*)(sm + SM_SRCS);

    const int tid  = threadIdx.x;
    const int wid  = tid >> 5;
    const int lane = tid & 31;
    const int c0   = blockIdx.x * M_TILE;

    if (tid < PK * 3) s_kpts[tid] = kernel_pts[tid];
    for (int i = tid; i < M_TILE * PK; i += NTH) s_coef[i] = 0.0f;
    __syncthreads();

    // ---- geometry ----
    #pragma unroll
    for (int j = 0; j < (M_TILE * PK) / NTH; j++) {
        int el = tid + j * NTH;
        int e  = c0 * PK + el;
        int s  = edge_src[e];
        int t  = edge_tgt[e];
        s_srcs[el] = s;
        float rx = pos[3 * t + 0] - pos[3 * s + 0];
        float ry = pos[3 * t + 1] - pos[3 * s + 1];
        float rz = pos[3 * t + 2] - pos[3 * s + 2];
        float best = 3.4e38f; int bk = 0;
        #pragma unroll
        for (int kp = 0; kp < PK; kp++) {
            float dx = rx - s_kpts[3 * kp + 0];
            float dy = ry - s_kpts[3 * kp + 1];
            float dz = rz - s_kpts[3 * kp + 2];
            float d2 = dx * dx + dy * dy + dz * dz;
            if (d2 < best) { best = d2; bk = kp; }
        }
        float w = fmaxf(1.0f - sqrtf(best) * 1.5f, 0.0f);
        atomicAdd(&s_coef[(el & ~(PK - 1)) + bk], w);
    }
    __syncthreads();

    // 4 warps, each owns all 32 rows x 32 cols (wnp = wid)
    const int wnp = wid;

    StepCtx ctx;
    ctx.sm = sm; ctx.smb = smb;
    ctx.x = x; ctx.s_srcs = s_srcs; ctx.s_coef = s_coef;
    ctx.arow = tid >> 2; ctx.aq = tid & 3; ctx.wnp = wnp; ctx.lane = lane;
    ctx.a_row_off0 = (uint32_t)((0  + (lane & 15)) * LDB + (lane >> 4) * 16);
    ctx.a_row_off1 = (uint32_t)((16 + (lane & 15)) * LDB + (lane >> 4) * 16);

    float acc[2][4][4];
    #pragma unroll
    for (int mt = 0; mt < 2; mt++)
        #pragma unroll
        for (int nt = 0; nt < 4; nt++)
            #pragma unroll
            for (int q = 0; q < 4; q++) acc[mt][nt][q] = 0.0f;

    const int arow = ctx.arow, aq = ctx.aq;
    float4 av[4];
    float  asc;
    uint4  b0[16], b1[16];

    // prologue: A[0] staged, B[0] -> b0
    {
        int src = s_srcs[arow * PK + 0];
        asc = s_coef[arow * PK + 0];
        const float4* xp = (const float4*)(x + (size_t)src * IN_F + aq * 16);
        #pragma unroll
        for (int j = 0; j < 4; j++) av[j] = xp[j];
        b_prefetch(b0, g_bfrag + wnp * 2048 + lane * 8);
        A_CVT_STORE(0);
    }
    __syncthreads();

    #pragma unroll 1
    for (int kk = 0; kk < PK; kk += 2) {
        gemm_step(kk,     b0, b1, ctx, av, asc, acc);
        gemm_step(kk + 1, b1, b0, ctx, av, asc, acc);
    }

    // ---- epilogue ----
    #pragma unroll
    for (int mt = 0; mt < 2; mt++) {
        int row = c0 + mt * 16 + (lane >> 2);
        #pragma unroll
        for (int nt = 0; nt < 4; nt++) {
            int col = wnp * 32 + nt * 8 + (lane & 3) * 2;
            float2 v0 = make_float2(acc[mt][nt][0], acc[mt][nt][1]);
            float2 v1 = make_float2(acc[mt][nt][2], acc[mt][nt][3]);
            *(float2*)(out + (size_t)row * OUT_F + col)       = v0;
            *(float2*)(out + (size_t)(row + 8) * OUT_F + col) = v1;
        }
    }
}

extern "C" void kernel_launch(void* const* d_in, const int* in_sizes, int n_in,
                              void* d_out, int out_size) {
    const float* x             = (const float*)d_in[0];
    const float* pos           = (const float*)d_in[1];
    const int*   edge_src      = (const int*)d_in[2];
    const int*   edge_tgt      = (const int*)d_in[3];
    const float* kernel_pts    = (const float*)d_in[4];
    const float* kernel_weight = (const float*)d_in[5];
    float* out = (float*)d_out;

    wpack_kernel<<<(PK * 8 * 2 * 2 * 32 * 8 + 255) / 256, 256>>>(kernel_weight);

    cudaFuncSetAttribute(kpconv_hmma_kernel,
                         cudaFuncAttributeMaxDynamicSharedMemorySize, SM_TOTAL);
    kpconv_hmma_kernel<<<NCENT / M_TILE, NTH, SM_TOTAL>>>(
        x, pos, edge_src, edge_tgt, kernel_pts, out);
}